// round 3
// baseline (speedup 1.0000x reference)
#include <cuda_runtime.h>

#define VOCAB   100000
#define BATCH   32
#define CAND    32768
#define ENCD    1024
#define HID     512
#define TOK     256

// Scratch (device globals — no allocation)
__device__ __align__(16) float g_h[BATCH * HID];
__device__ __align__(16) float g_qt2[TOK * BATCH];      // [k2][b][2] : pair-transposed q
__device__ __align__(16) float g_P[(size_t)VOCAB * BATCH]; // [t][b]

static __device__ __forceinline__ unsigned long long ffma2(
    unsigned long long a, unsigned long long b, unsigned long long c) {
    unsigned long long d;
    asm("fma.rn.f32x2 %0, %1, %2, %3;" : "=l"(d) : "l"(a), "l"(b), "l"(c));
    return d;
}

static __device__ __forceinline__ float pair_sum(unsigned long long v) {
    union { unsigned long long u; float2 f; } x; x.u = v;
    return x.f.x + x.f.y;
}

// ---------------------------------------------------------------------------
// K1: h[b][j] = gelu(enc[b] . W1[j] + b1[j]),  grid (16 j-tiles, 8 b-tiles), 128 thr
// ---------------------------------------------------------------------------
__global__ void k1_hidden(const float* __restrict__ enc,
                          const float* __restrict__ W1,
                          const float* __restrict__ b1) {
    __shared__ float es[4 * ENCD];
    const int tid = threadIdx.x;
    const int bb0 = blockIdx.y * 4;

    const float4* enc4 = (const float4*)enc;
    float4* es4 = (float4*)es;
#pragma unroll
    for (int i = 0; i < 8; i++) {
        int f4 = i * 128 + tid;              // 1024 float4 total
        int r = f4 >> 8, k4 = f4 & 255;
        es4[f4] = enc4[(bb0 + r) * 256 + k4];
    }
    __syncthreads();

    const int w = tid >> 5, lane = tid & 31;
    const float4* W14 = (const float4*)W1;

    for (int jj = 0; jj < 8; jj++) {
        int j = blockIdx.x * 32 + w * 8 + jj;
        float acc[4] = {0.f, 0.f, 0.f, 0.f};
#pragma unroll
        for (int i = 0; i < 8; i++) {
            float4 wv = W14[j * 256 + i * 32 + lane];
#pragma unroll
            for (int bbi = 0; bbi < 4; bbi++) {
                float4 ev = es4[bbi * 256 + i * 32 + lane];
                acc[bbi] += wv.x * ev.x + wv.y * ev.y + wv.z * ev.z + wv.w * ev.w;
            }
        }
#pragma unroll
        for (int bbi = 0; bbi < 4; bbi++) {
            float v = acc[bbi];
#pragma unroll
            for (int off = 16; off > 0; off >>= 1)
                v += __shfl_xor_sync(0xFFFFFFFFu, v, off);
            if (lane == 0) {
                float x = v + b1[j];
                float g = 0.5f * x * (1.0f + erff(x * 0.70710678118654752f));
                g_h[(bb0 + bbi) * HID + j] = g;
            }
        }
    }
}

// ---------------------------------------------------------------------------
// K2: q[b][d] = h[b] . W2[d]; store pair-transposed g_qt2[(d>>1)*64 + b*2 + (d&1)]
//     grid (8 d-tiles, 8 b-tiles), 128 thr
// ---------------------------------------------------------------------------
__global__ void k2_query(const float* __restrict__ W2) {
    __shared__ float hs[4 * HID];
    const int tid = threadIdx.x;
    const int bb0 = blockIdx.y * 4;

    const float4* h4 = (const float4*)g_h;
    float4* hs4 = (float4*)hs;
#pragma unroll
    for (int i = 0; i < 4; i++) {
        int f4 = i * 128 + tid;              // 512 float4
        int r = f4 >> 7, k4 = f4 & 127;
        hs4[f4] = h4[(bb0 + r) * 128 + k4];
    }
    __syncthreads();

    const int w = tid >> 5, lane = tid & 31;
    const float4* W24 = (const float4*)W2;

    for (int dd = 0; dd < 8; dd++) {
        int d = blockIdx.x * 32 + w * 8 + dd;
        float acc[4] = {0.f, 0.f, 0.f, 0.f};
#pragma unroll
        for (int i = 0; i < 4; i++) {
            float4 wv = W24[d * 128 + i * 32 + lane];
#pragma unroll
            for (int bbi = 0; bbi < 4; bbi++) {
                float4 hv = hs4[bbi * 128 + i * 32 + lane];
                acc[bbi] += wv.x * hv.x + wv.y * hv.y + wv.z * hv.z + wv.w * hv.w;
            }
        }
#pragma unroll
        for (int bbi = 0; bbi < 4; bbi++) {
            float v = acc[bbi];
#pragma unroll
            for (int off = 16; off > 0; off >>= 1)
                v += __shfl_xor_sync(0xFFFFFFFFu, v, off);
            if (lane == 0)
                g_qt2[(d >> 1) * 64 + (bb0 + bbi) * 2 + (d & 1)] = v;
        }
    }
}

// ---------------------------------------------------------------------------
// K3: P[t][b] = tok_emb[t] . q[b]   (the big one)
//     block = 128 thr, tile = 128 t-rows x 32 b, K staged in 64-wide chunks.
//     Thread = 8 t-rows x 4 b; accumulators are f32x2 over k-pairs (FFMA2).
//     smem: qs = full q, pair-transposed [k2][32b-pairs] (32 KB)
//           as = A chunk  [128][64] (32 KB)
// ---------------------------------------------------------------------------
__global__ void __launch_bounds__(128) k3_gemm(const float* __restrict__ tok) {
    extern __shared__ float sm[];
    float* qs = sm;                 // 8192 floats
    float* as = sm + 8192;          // 8192 floats

    const int tid = threadIdx.x;
    const int tg = tid >> 3;        // 0..15 -> 8 rows each
    const int bg = tid & 7;         // 0..7  -> 4 b each
    const int t0 = blockIdx.x * 128;

    // Load full q (pair-transposed) into smem
    {
        const float4* qg4 = (const float4*)g_qt2;
        float4* qs4 = (float4*)qs;
#pragma unroll
        for (int i = 0; i < 16; i++)
            qs4[i * 128 + tid] = qg4[i * 128 + tid];
    }

    unsigned long long acc[8][4];
#pragma unroll
    for (int ti = 0; ti < 8; ti++)
#pragma unroll
        for (int bi = 0; bi < 4; bi++) acc[ti][bi] = 0ULL;

    const float4* tok4 = (const float4*)tok;
    float4* as4 = (float4*)as;
    const ulonglong2* as_u = (const ulonglong2*)as;
    const ulonglong2* qs_u = (const ulonglong2*)qs;

    for (int cch = 0; cch < 4; cch++) {
        __syncthreads();   // covers q-load on first pass, compute-done on later passes
#pragma unroll
        for (int i = 0; i < 16; i++) {
            int f4 = i * 128 + tid;          // 2048 float4 in the chunk
            int r = f4 >> 4, c4 = f4 & 15;
            int t = t0 + r;
            if (t > VOCAB - 1) t = VOCAB - 1;
            as4[r * 16 + c4] = tok4[(size_t)t * 64 + cch * 16 + c4];
        }
        __syncthreads();

#pragma unroll 4
        for (int k4 = 0; k4 < 16; k4++) {
            int k2 = cch * 32 + k4 * 2;
            // q pairs for 4 b's, two k-pairs
            ulonglong2 q0a = qs_u[(k2 + 0) * 16 + bg * 2];
            ulonglong2 q0b = qs_u[(k2 + 0) * 16 + bg * 2 + 1];
            ulonglong2 q1a = qs_u[(k2 + 1) * 16 + bg * 2];
            ulonglong2 q1b = qs_u[(k2 + 1) * 16 + bg * 2 + 1];
#pragma unroll
            for (int ti = 0; ti < 8; ti++) {
                ulonglong2 av = as_u[(tg * 8 + ti) * 16 + k4];
                acc[ti][0] = ffma2(av.x, q0a.x, acc[ti][0]);
                acc[ti][1] = ffma2(av.x, q0a.y, acc[ti][1]);
                acc[ti][2] = ffma2(av.x, q0b.x, acc[ti][2]);
                acc[ti][3] = ffma2(av.x, q0b.y, acc[ti][3]);
                acc[ti][0] = ffma2(av.y, q1a.x, acc[ti][0]);
                acc[ti][1] = ffma2(av.y, q1a.y, acc[ti][1]);
                acc[ti][2] = ffma2(av.y, q1b.x, acc[ti][2]);
                acc[ti][3] = ffma2(av.y, q1b.y, acc[ti][3]);
            }
        }
    }

    float4* P4 = (float4*)g_P;
#pragma unroll
    for (int ti = 0; ti < 8; ti++) {
        int t = t0 + tg * 8 + ti;
        if (t < VOCAB) {
            float4 r;
            r.x = pair_sum(acc[ti][0]);
            r.y = pair_sum(acc[ti][1]);
            r.z = pair_sum(acc[ti][2]);
            r.w = pair_sum(acc[ti][3]);
            P4[(size_t)t * 8 + bg] = r;
        }
    }
}

// ---------------------------------------------------------------------------
// K4: logits[b][c] = P[cand[b][c]][b]   (cand is int32 — JAX x64 disabled)
// ---------------------------------------------------------------------------
__global__ void k4_gather(const int* __restrict__ cand,
                          float* __restrict__ out) {
    int g = blockIdx.x * 256 + threadIdx.x;
    int t = cand[g];
    // defensive clamp (tokens are 0..VOCAB-1 by construction; this is ~free)
    t = (t < 0) ? 0 : (t >= VOCAB ? VOCAB - 1 : t);
    int b = g >> 15;                 // C = 32768
    out[g] = g_P[(size_t)t * 32 + b];
}

// ---------------------------------------------------------------------------
extern "C" void kernel_launch(void* const* d_in, const int* in_sizes, int n_in,
                              void* d_out, int out_size) {
    const float* enc  = (const float*)d_in[0];
    const int*   cand = (const int*)d_in[1];
    const float* tok  = (const float*)d_in[2];
    const float* W1   = (const float*)d_in[3];
    const float* b1   = (const float*)d_in[4];
    const float* W2   = (const float*)d_in[5];
    float* out = (float*)d_out;

    cudaFuncSetAttribute(k3_gemm, cudaFuncAttributeMaxDynamicSharedMemorySize, 65536);

    k1_hidden<<<dim3(16, 8), 128>>>(enc, W1, b1);
    k2_query<<<dim3(8, 8), 128>>>(W2);
    k3_gemm<<<(VOCAB + 127) / 128, 128, 65536>>>(tok);
    k4_gather<<<(BATCH * CAND) / 256, 256>>>(cand, out);
}

// round 4
// speedup vs baseline: 1.0662x; 1.0662x over previous
#include <cuda_runtime.h>

#define VOCAB   100000
#define BATCH   32
#define CAND    32768
#define ENCD    1024
#define HID     512
#define TOK     256

#define K3_ROWS 256            // t-rows per block
#define K3_KCH  32             // K floats per chunk (16 k-pairs)
#define K3_KP   (K3_KCH / 2)   // k-pairs per chunk
#define AT_STRIDE 257          // ulonglongs per kpair row (256 rows + 1 pad)

// Scratch (device globals — no allocation)
__device__ __align__(16) float g_h[BATCH * HID];
__device__ __align__(16) float g_qt2[TOK * BATCH];          // [kpair][b][2]
__device__ __align__(16) float g_P[(size_t)VOCAB * BATCH];  // [t][b]

static __device__ __forceinline__ unsigned long long ffma2(
    unsigned long long a, unsigned long long b, unsigned long long c) {
    unsigned long long d;
    asm("fma.rn.f32x2 %0, %1, %2, %3;" : "=l"(d) : "l"(a), "l"(b), "l"(c));
    return d;
}

static __device__ __forceinline__ float pair_sum(unsigned long long v) {
    union { unsigned long long u; float2 f; } x; x.u = v;
    return x.f.x + x.f.y;
}

// ---------------------------------------------------------------------------
// K1: h[b][j] = gelu(enc[b] . W1[j] + b1[j])
// ---------------------------------------------------------------------------
__global__ void k1_hidden(const float* __restrict__ enc,
                          const float* __restrict__ W1,
                          const float* __restrict__ b1) {
    __shared__ float es[4 * ENCD];
    const int tid = threadIdx.x;
    const int bb0 = blockIdx.y * 4;

    const float4* enc4 = (const float4*)enc;
    float4* es4 = (float4*)es;
#pragma unroll
    for (int i = 0; i < 8; i++) {
        int f4 = i * 128 + tid;
        int r = f4 >> 8, k4 = f4 & 255;
        es4[f4] = enc4[(bb0 + r) * 256 + k4];
    }
    __syncthreads();

    const int w = tid >> 5, lane = tid & 31;
    const float4* W14 = (const float4*)W1;

    for (int jj = 0; jj < 8; jj++) {
        int j = blockIdx.x * 32 + w * 8 + jj;
        float acc[4] = {0.f, 0.f, 0.f, 0.f};
#pragma unroll
        for (int i = 0; i < 8; i++) {
            float4 wv = W14[j * 256 + i * 32 + lane];
#pragma unroll
            for (int bbi = 0; bbi < 4; bbi++) {
                float4 ev = es4[bbi * 256 + i * 32 + lane];
                acc[bbi] += wv.x * ev.x + wv.y * ev.y + wv.z * ev.z + wv.w * ev.w;
            }
        }
#pragma unroll
        for (int bbi = 0; bbi < 4; bbi++) {
            float v = acc[bbi];
#pragma unroll
            for (int off = 16; off > 0; off >>= 1)
                v += __shfl_xor_sync(0xFFFFFFFFu, v, off);
            if (lane == 0) {
                float x = v + b1[j];
                float g = 0.5f * x * (1.0f + erff(x * 0.70710678118654752f));
                g_h[(bb0 + bbi) * HID + j] = g;
            }
        }
    }
}

// ---------------------------------------------------------------------------
// K2: q[b][d] = h[b] . W2[d]; stored pair-transposed [d>>1][b][d&1]
// ---------------------------------------------------------------------------
__global__ void k2_query(const float* __restrict__ W2) {
    __shared__ float hs[4 * HID];
    const int tid = threadIdx.x;
    const int bb0 = blockIdx.y * 4;

    const float4* h4 = (const float4*)g_h;
    float4* hs4 = (float4*)hs;
#pragma unroll
    for (int i = 0; i < 4; i++) {
        int f4 = i * 128 + tid;
        int r = f4 >> 7, k4 = f4 & 127;
        hs4[f4] = h4[(bb0 + r) * 128 + k4];
    }
    __syncthreads();

    const int w = tid >> 5, lane = tid & 31;
    const float4* W24 = (const float4*)W2;

    for (int dd = 0; dd < 8; dd++) {
        int d = blockIdx.x * 32 + w * 8 + dd;
        float acc[4] = {0.f, 0.f, 0.f, 0.f};
#pragma unroll
        for (int i = 0; i < 4; i++) {
            float4 wv = W24[d * 128 + i * 32 + lane];
#pragma unroll
            for (int bbi = 0; bbi < 4; bbi++) {
                float4 hv = hs4[bbi * 128 + i * 32 + lane];
                acc[bbi] += wv.x * hv.x + wv.y * hv.y + wv.z * hv.z + wv.w * hv.w;
            }
        }
#pragma unroll
        for (int bbi = 0; bbi < 4; bbi++) {
            float v = acc[bbi];
#pragma unroll
            for (int off = 16; off > 0; off >>= 1)
                v += __shfl_xor_sync(0xFFFFFFFFu, v, off);
            if (lane == 0)
                g_qt2[(d >> 1) * 64 + (bb0 + bbi) * 2 + (d & 1)] = v;
        }
    }
}

// ---------------------------------------------------------------------------
// K3: P[t][b] = tok_emb[t] . q[b]
//   block = 128 thr (LB 128,2), tile = 256 t x 32 b, thread = 8t x 8b (f32x2 accs)
//   smem: qs  = full q [128 kpairs][32 b] f32x2                    (32 KB)
//         at  = A chunk transposed [16 kpairs][256 rows + pad] f32x2 (32.9 KB)
//   A reads row-interleaved (tg + s*32, 8B) -> conflict-free + 4x lane dedup.
// ---------------------------------------------------------------------------
__global__ void __launch_bounds__(128, 2) k3_gemm(const float* __restrict__ tok) {
    extern __shared__ unsigned long long sm_u[];
    unsigned long long* qs = sm_u;                    // 4096 ullong
    unsigned long long* at = sm_u + 4096;             // 16 * 257 ullong

    const int tid = threadIdx.x;
    const int bg  = tid & 3;          // 4 b-groups of 8 b
    const int tg  = tid >> 2;         // 32 t-groups, rows tg + s*32
    const int t0  = blockIdx.x * K3_ROWS;

    // Load full q into smem (2048 float4)
    {
        const float4* qg4 = (const float4*)g_qt2;
        float4* qs4 = (float4*)qs;
#pragma unroll
        for (int i = 0; i < 16; i++)
            qs4[i * 128 + tid] = qg4[i * 128 + tid];
    }

    unsigned long long acc[8][8];
#pragma unroll
    for (int s = 0; s < 8; s++)
#pragma unroll
        for (int b = 0; b < 8; b++) acc[s][b] = 0ULL;

    const float4* tok4 = (const float4*)tok;

    for (int cch = 0; cch < 8; cch++) {
        __syncthreads();   // q-load done (first pass) / compute done (later)
        // Stage A chunk transposed: [kpair_local][row], padded rows
#pragma unroll
        for (int i = 0; i < 16; i++) {
            int f4 = i * 128 + tid;          // 2048 float4 in chunk (256 rows x 8 f4)
            int r  = f4 >> 3, c4 = f4 & 7;
            int t  = t0 + r;
            if (t > VOCAB - 1) t = VOCAB - 1;
            float4 v = tok4[(size_t)t * 64 + cch * 8 + c4];
            union { float2 f; unsigned long long u; } p0, p1;
            p0.f.x = v.x; p0.f.y = v.y;
            p1.f.x = v.z; p1.f.y = v.w;
            at[(c4 * 2 + 0) * AT_STRIDE + r] = p0.u;
            at[(c4 * 2 + 1) * AT_STRIDE + r] = p1.u;
        }
        __syncthreads();

        const unsigned long long* qrow0 = qs + cch * K3_KP * 32 + bg * 8;
#pragma unroll 2
        for (int k2 = 0; k2 < K3_KP; k2++) {
            const unsigned long long* qr = qrow0 + k2 * 32;
            unsigned long long qv[8];
#pragma unroll
            for (int b = 0; b < 8; b++) qv[b] = qr[b];

            const unsigned long long* ar = at + k2 * AT_STRIDE + tg;
            unsigned long long av[8];
#pragma unroll
            for (int s = 0; s < 8; s++) av[s] = ar[s * 32];

#pragma unroll
            for (int s = 0; s < 8; s++)
#pragma unroll
                for (int b = 0; b < 8; b++)
                    acc[s][b] = ffma2(av[s], qv[b], acc[s][b]);
        }
    }

    float4* P4 = (float4*)g_P;
#pragma unroll
    for (int s = 0; s < 8; s++) {
        int t = t0 + tg + s * 32;
        if (t < VOCAB) {
            float4 r0, r1;
            r0.x = pair_sum(acc[s][0]); r0.y = pair_sum(acc[s][1]);
            r0.z = pair_sum(acc[s][2]); r0.w = pair_sum(acc[s][3]);
            r1.x = pair_sum(acc[s][4]); r1.y = pair_sum(acc[s][5]);
            r1.z = pair_sum(acc[s][6]); r1.w = pair_sum(acc[s][7]);
            P4[(size_t)t * 8 + bg * 2 + 0] = r0;
            P4[(size_t)t * 8 + bg * 2 + 1] = r1;
        }
    }
}

// ---------------------------------------------------------------------------
// K4: logits[b][c] = P[cand[b][c]][b], 4 elems/thread for MLP
// ---------------------------------------------------------------------------
__global__ void k4_gather(const int* __restrict__ cand,
                          float* __restrict__ out) {
    int base = blockIdx.x * 256 + threadIdx.x;   // 1024 blocks x 256 thr
    int t[4];
#pragma unroll
    for (int j = 0; j < 4; j++) {
        int tt = cand[base + j * 262144];
        t[j] = (tt < 0) ? 0 : (tt >= VOCAB ? VOCAB - 1 : tt);
    }
    float v[4];
#pragma unroll
    for (int j = 0; j < 4; j++) {
        int g = base + j * 262144;
        int b = g >> 15;
        v[j] = g_P[(size_t)t[j] * 32 + b];
    }
#pragma unroll
    for (int j = 0; j < 4; j++)
        out[base + j * 262144] = v[j];
}

// ---------------------------------------------------------------------------
extern "C" void kernel_launch(void* const* d_in, const int* in_sizes, int n_in,
                              void* d_out, int out_size) {
    const float* enc  = (const float*)d_in[0];
    const int*   cand = (const int*)d_in[1];
    const float* tok  = (const float*)d_in[2];
    const float* W1   = (const float*)d_in[3];
    const float* b1   = (const float*)d_in[4];
    const float* W2   = (const float*)d_in[5];
    float* out = (float*)d_out;

    const int k3_smem = (4096 + 16 * AT_STRIDE) * 8;   // 65,672 B
    cudaFuncSetAttribute(k3_gemm, cudaFuncAttributeMaxDynamicSharedMemorySize, k3_smem);

    k1_hidden<<<dim3(16, 8), 128>>>(enc, W1, b1);
    k2_query<<<dim3(8, 8), 128>>>(W2);
    k3_gemm<<<(VOCAB + K3_ROWS - 1) / K3_ROWS, 128, k3_smem>>>(tok);
    k4_gather<<<1024, 256>>>(cand, out);
}

// round 6
// speedup vs baseline: 1.5990x; 1.4997x over previous
#include <cuda_runtime.h>
#include <cuda_bf16.h>
#include <cstdint>

#define VOCAB   100000
#define BATCH   32
#define CAND    32768
#define ENCD    1024
#define HID     512
#define TOK     256

// ---------------- scratch ----------------
__device__ __align__(16) float g_h[BATCH * HID];
__device__ __align__(16) __nv_bfloat16 g_qh[BATCH * TOK];   // [b][d] hi split
__device__ __align__(16) __nv_bfloat16 g_ql[BATCH * TOK];   // [b][d] lo split
__device__ __align__(16) float g_P[(size_t)VOCAB * BATCH];  // [t][b]

static __device__ __forceinline__ uint32_t b2pack(__nv_bfloat16 a, __nv_bfloat16 b) {
    uint16_t ua = *(uint16_t*)&a, ub = *(uint16_t*)&b;
    return (uint32_t)ua | ((uint32_t)ub << 16);
}

// mma.sync m16n8k16 row.col f32 += bf16 * bf16  (base-target PTX, sm_80+)
static __device__ __forceinline__ void mma16816(float c[4],
                                                const uint32_t a[4],
                                                const uint32_t b[2]) {
    asm volatile(
        "mma.sync.aligned.m16n8k16.row.col.f32.bf16.bf16.f32 "
        "{%0,%1,%2,%3}, {%4,%5,%6,%7}, {%8,%9}, {%0,%1,%2,%3};"
        : "+f"(c[0]), "+f"(c[1]), "+f"(c[2]), "+f"(c[3])
        : "r"(a[0]), "r"(a[1]), "r"(a[2]), "r"(a[3]), "r"(b[0]), "r"(b[1]));
}

// ---------------------------------------------------------------------------
// K1: h[b][j] = gelu(enc[b] . W1[j] + b1[j])
// ---------------------------------------------------------------------------
__global__ void k1_hidden(const float* __restrict__ enc,
                          const float* __restrict__ W1,
                          const float* __restrict__ b1) {
    __shared__ float es[4 * ENCD];
    const int tid = threadIdx.x;
    const int bb0 = blockIdx.y * 4;

    const float4* enc4 = (const float4*)enc;
    float4* es4 = (float4*)es;
#pragma unroll
    for (int i = 0; i < 8; i++) {
        int f4 = i * 128 + tid;
        int r = f4 >> 8, k4 = f4 & 255;
        es4[f4] = enc4[(bb0 + r) * 256 + k4];
    }
    __syncthreads();

    const int w = tid >> 5, lane = tid & 31;
    const float4* W14 = (const float4*)W1;

    for (int jj = 0; jj < 8; jj++) {
        int j = blockIdx.x * 32 + w * 8 + jj;
        float acc[4] = {0.f, 0.f, 0.f, 0.f};
#pragma unroll
        for (int i = 0; i < 8; i++) {
            float4 wv = W14[j * 256 + i * 32 + lane];
#pragma unroll
            for (int bbi = 0; bbi < 4; bbi++) {
                float4 ev = es4[bbi * 256 + i * 32 + lane];
                acc[bbi] += wv.x * ev.x + wv.y * ev.y + wv.z * ev.z + wv.w * ev.w;
            }
        }
#pragma unroll
        for (int bbi = 0; bbi < 4; bbi++) {
            float v = acc[bbi];
#pragma unroll
            for (int off = 16; off > 0; off >>= 1)
                v += __shfl_xor_sync(0xFFFFFFFFu, v, off);
            if (lane == 0) {
                float x = v + b1[j];
                float g = 0.5f * x * (1.0f + erff(x * 0.70710678118654752f));
                g_h[(bb0 + bbi) * HID + j] = g;
            }
        }
    }
}

// ---------------------------------------------------------------------------
// K2: q[b][d] = h[b] . W2[d]; store as bf16 hi/lo splits, row-major [b][d]
// ---------------------------------------------------------------------------
__global__ void k2_query(const float* __restrict__ W2) {
    __shared__ float hs[4 * HID];
    const int tid = threadIdx.x;
    const int bb0 = blockIdx.y * 4;

    const float4* h4 = (const float4*)g_h;
    float4* hs4 = (float4*)hs;
#pragma unroll
    for (int i = 0; i < 4; i++) {
        int f4 = i * 128 + tid;
        int r = f4 >> 7, k4 = f4 & 127;
        hs4[f4] = h4[(bb0 + r) * 128 + k4];
    }
    __syncthreads();

    const int w = tid >> 5, lane = tid & 31;
    const float4* W24 = (const float4*)W2;

    for (int dd = 0; dd < 8; dd++) {
        int d = blockIdx.x * 32 + w * 8 + dd;
        float acc[4] = {0.f, 0.f, 0.f, 0.f};
#pragma unroll
        for (int i = 0; i < 4; i++) {
            float4 wv = W24[d * 128 + i * 32 + lane];
#pragma unroll
            for (int bbi = 0; bbi < 4; bbi++) {
                float4 hv = hs4[bbi * 128 + i * 32 + lane];
                acc[bbi] += wv.x * hv.x + wv.y * hv.y + wv.z * hv.z + wv.w * hv.w;
            }
        }
#pragma unroll
        for (int bbi = 0; bbi < 4; bbi++) {
            float v = acc[bbi];
#pragma unroll
            for (int off = 16; off > 0; off >>= 1)
                v += __shfl_xor_sync(0xFFFFFFFFu, v, off);
            if (lane == 0) {
                int b = bb0 + bbi;
                __nv_bfloat16 h = __float2bfloat16(v);
                g_qh[b * TOK + d] = h;
                g_ql[b * TOK + d] = __float2bfloat16(v - __bfloat162float(h));
            }
        }
    }
}

// ---------------------------------------------------------------------------
// K3m: P[t][b] = tok_emb[t] . q[b] via mma.sync bf16 3-pass split.
//   block = 128 thr (4 warps), M=128 rows, N=32, K=256 in four 64-chunks.
//   Warp w owns rows [w*32, w*32+32) x all 32 b.
//   smem (padded, analytically conflict-free fragment loads):
//     q hi/lo: 32 rows x 264 bf16 (528B stride)   = 16896 B each
//     A hi/lo: 128 rows x 72 bf16 (144B stride)   = 18432 B each
// ---------------------------------------------------------------------------
#define QROW_W 132          // 32-bit words per q row (264 bf16)
#define AROW_W 36           // 32-bit words per A row (72 bf16)
#define SM_QH  0
#define SM_QL  16896
#define SM_AH  33792
#define SM_AL  52224
#define SM_TOT 70656

__global__ void __launch_bounds__(128, 2) k3_mma(const float* __restrict__ tok) {
    extern __shared__ char sm[];
    uint32_t* qh = (uint32_t*)(sm + SM_QH);
    uint32_t* ql = (uint32_t*)(sm + SM_QL);
    uint32_t* ah = (uint32_t*)(sm + SM_AH);
    uint32_t* al = (uint32_t*)(sm + SM_AL);

    const int tid  = threadIdx.x;
    const int warp = tid >> 5, lane = tid & 31;
    const int gr   = lane >> 2;          // fragment row group 0..7
    const int kq   = lane & 3;           // fragment k quarter
    const int t0   = blockIdx.x * 128;

    // Stage q hi/lo into padded smem (2048 uint2 = 8192 bf16 per array)
    {
        const uint2* gq = (const uint2*)g_qh;
        const uint2* gl = (const uint2*)g_ql;
#pragma unroll
        for (int i = 0; i < 16; i++) {
            int idx2 = i * 128 + tid;         // 0..2047 (4 bf16 each)
            int n = idx2 >> 6;                // b row 0..31
            int k2 = (idx2 & 63) * 2;         // word offset in row
            *(uint2*)&qh[n * QROW_W + k2] = gq[idx2];
            *(uint2*)&ql[n * QROW_W + k2] = gl[idx2];
        }
    }

    float acc[2][4][4];
#pragma unroll
    for (int mt = 0; mt < 2; mt++)
#pragma unroll
        for (int nt = 0; nt < 4; nt++)
#pragma unroll
            for (int r = 0; r < 4; r++) acc[mt][nt][r] = 0.f;

    const float4* tok4 = (const float4*)tok;
    const int r0 = warp * 32;

    for (int cch = 0; cch < 4; cch++) {
        __syncthreads();   // q staged (first pass) / A consumed (later passes)
        // Stage A chunk: 128 rows x 64 fp32 -> bf16 hi/lo, 144B padded rows
#pragma unroll
        for (int i = 0; i < 16; i++) {
            int f4 = i * 128 + tid;           // 2048 float4 (128 rows x 16)
            int r = f4 >> 4, c4 = f4 & 15;
            int t = t0 + r; if (t > VOCAB - 1) t = VOCAB - 1;
            float4 v = __ldcs(&tok4[(size_t)t * 64 + cch * 16 + c4]);
            __nv_bfloat16 h0 = __float2bfloat16(v.x);
            __nv_bfloat16 h1 = __float2bfloat16(v.y);
            __nv_bfloat16 h2 = __float2bfloat16(v.z);
            __nv_bfloat16 h3 = __float2bfloat16(v.w);
            uint2 hv, lv;
            hv.x = b2pack(h0, h1); hv.y = b2pack(h2, h3);
            lv.x = b2pack(__float2bfloat16(v.x - __bfloat162float(h0)),
                          __float2bfloat16(v.y - __bfloat162float(h1)));
            lv.y = b2pack(__float2bfloat16(v.z - __bfloat162float(h2)),
                          __float2bfloat16(v.w - __bfloat162float(h3)));
            *(uint2*)&ah[r * AROW_W + c4 * 2] = hv;
            *(uint2*)&al[r * AROW_W + c4 * 2] = lv;
        }
        __syncthreads();

#pragma unroll
        for (int kt = 0; kt < 4; kt++) {
            // B fragments (q): b0 = {q[n][k0+kq*2], +1}, b1 = +8 k
            uint32_t bh[4][2], bl[4][2];
            const int qw = cch * 32 + kt * 8 + kq;
#pragma unroll
            for (int nt = 0; nt < 4; nt++) {
                int w0 = (nt * 8 + gr) * QROW_W + qw;
                bh[nt][0] = qh[w0]; bh[nt][1] = qh[w0 + 4];
                bl[nt][0] = ql[w0]; bl[nt][1] = ql[w0 + 4];
            }
            // A fragments: a0 = {A[r][k0+kq*2],+1}, a1 = row+8, a2 = k+8, a3 = both
            uint32_t fah[2][4], fal[2][4];
            const int aw = kt * 8 + kq;
#pragma unroll
            for (int mt = 0; mt < 2; mt++) {
                int w = (r0 + mt * 16 + gr) * AROW_W + aw;
                fah[mt][0] = ah[w];
                fah[mt][1] = ah[w + 8 * AROW_W];
                fah[mt][2] = ah[w + 4];
                fah[mt][3] = ah[w + 8 * AROW_W + 4];
                fal[mt][0] = al[w];
                fal[mt][1] = al[w + 8 * AROW_W];
                fal[mt][2] = al[w + 4];
                fal[mt][3] = al[w + 8 * AROW_W + 4];
            }
#pragma unroll
            for (int mt = 0; mt < 2; mt++)
#pragma unroll
                for (int nt = 0; nt < 4; nt++) {
                    mma16816(acc[mt][nt], fah[mt], bh[nt]);
                    mma16816(acc[mt][nt], fah[mt], bl[nt]);
                    mma16816(acc[mt][nt], fal[mt], bh[nt]);
                }
        }
    }

    // Epilogue: c0,c1 -> P[t0+r0+mt*16+gr][nt*8+kq*2 ..+1]; c2,c3 -> row+8
#pragma unroll
    for (int mt = 0; mt < 2; mt++) {
        int ta = t0 + r0 + mt * 16 + gr;
        int tb = ta + 8;
#pragma unroll
        for (int nt = 0; nt < 4; nt++) {
            int col = nt * 8 + kq * 2;
            if (ta < VOCAB)
                *(float2*)&g_P[(size_t)ta * 32 + col] = make_float2(acc[mt][nt][0], acc[mt][nt][1]);
            if (tb < VOCAB)
                *(float2*)&g_P[(size_t)tb * 32 + col] = make_float2(acc[mt][nt][2], acc[mt][nt][3]);
        }
    }
}

// ---------------------------------------------------------------------------
// K4: logits[b][c] = P[cand[b][c]][b], 4 elems/thread for MLP
// ---------------------------------------------------------------------------
__global__ void k4_gather(const int* __restrict__ cand,
                          float* __restrict__ out) {
    int base = blockIdx.x * 256 + threadIdx.x;   // 1024 blocks x 256 thr
    int t[4];
#pragma unroll
    for (int j = 0; j < 4; j++) {
        int tt = __ldcs(&cand[base + j * 262144]);
        t[j] = (tt < 0) ? 0 : (tt >= VOCAB ? VOCAB - 1 : tt);
    }
    float v[4];
#pragma unroll
    for (int j = 0; j < 4; j++) {
        int g = base + j * 262144;
        int b = g >> 15;
        v[j] = g_P[(size_t)t[j] * 32 + b];
    }
#pragma unroll
    for (int j = 0; j < 4; j++)
        out[base + j * 262144] = v[j];
}

// ---------------------------------------------------------------------------
extern "C" void kernel_launch(void* const* d_in, const int* in_sizes, int n_in,
                              void* d_out, int out_size) {
    const float* enc  = (const float*)d_in[0];
    const int*   cand = (const int*)d_in[1];
    const float* tok  = (const float*)d_in[2];
    const float* W1   = (const float*)d_in[3];
    const float* b1   = (const float*)d_in[4];
    const float* W2   = (const float*)d_in[5];
    float* out = (float*)d_out;

    cudaFuncSetAttribute(k3_mma, cudaFuncAttributeMaxDynamicSharedMemorySize, SM_TOT);

    k1_hidden<<<dim3(16, 8), 128>>>(enc, W1, b1);
    k2_query<<<dim3(8, 8), 128>>>(W2);
    k3_mma<<<(VOCAB + 127) / 128, 128, SM_TOT>>>(tok);
    k4_gather<<<1024, 256>>>(cand, out);
}

// round 7
// speedup vs baseline: 1.7580x; 1.0994x over previous
#include <cuda_runtime.h>
#include <cuda_bf16.h>
#include <cstdint>

#define VOCAB   100000
#define BATCH   32
#define CAND    32768
#define ENCD    1024
#define HID     512
#define TOK     256

// ---------------- scratch ----------------
__device__ __align__(16) float g_h[BATCH * HID];
__device__ __align__(16) __nv_bfloat16 g_qh[BATCH * TOK];   // [b][d] hi split
__device__ __align__(16) __nv_bfloat16 g_ql[BATCH * TOK];   // [b][d] lo split
__device__ __align__(16) float g_P[(size_t)VOCAB * BATCH];  // [t][b]

// mma.sync m16n8k16 row.col f32 += bf16 * bf16  (base-target PTX, sm_80+)
static __device__ __forceinline__ void mma16816(float c[4],
                                                const uint32_t a[4],
                                                const uint32_t b[2]) {
    asm volatile(
        "mma.sync.aligned.m16n8k16.row.col.f32.bf16.bf16.f32 "
        "{%0,%1,%2,%3}, {%4,%5,%6,%7}, {%8,%9}, {%0,%1,%2,%3};"
        : "+f"(c[0]), "+f"(c[1]), "+f"(c[2]), "+f"(c[3])
        : "r"(a[0]), "r"(a[1]), "r"(a[2]), "r"(a[3]), "r"(b[0]), "r"(b[1]));
}

// fp32 pair -> bf16x2 hi (packed cvt) + bf16x2 lo (exact residual). x -> low 16.
static __device__ __forceinline__ void cvt_split(float x, float y,
                                                 uint32_t& hi, uint32_t& lo) {
    asm("cvt.rn.bf16x2.f32 %0, %1, %2;" : "=r"(hi) : "f"(y), "f"(x));
    float hx = __uint_as_float(hi << 16);            // exact bf16->f32
    float hy = __uint_as_float(hi & 0xFFFF0000u);
    float rx = x - hx, ry = y - hy;                  // exact residual
    asm("cvt.rn.bf16x2.f32 %0, %1, %2;" : "=r"(lo) : "f"(ry), "f"(rx));
}

static __device__ __forceinline__ uint32_t b2pack(__nv_bfloat16 a, __nv_bfloat16 b) {
    uint16_t ua = *(uint16_t*)&a, ub = *(uint16_t*)&b;
    return (uint32_t)ua | ((uint32_t)ub << 16);
}

// ---------------------------------------------------------------------------
// K1: h[b][j] = gelu(enc[b] . W1[j] + b1[j])
// ---------------------------------------------------------------------------
__global__ void k1_hidden(const float* __restrict__ enc,
                          const float* __restrict__ W1,
                          const float* __restrict__ b1) {
    __shared__ float es[4 * ENCD];
    const int tid = threadIdx.x;
    const int bb0 = blockIdx.y * 4;

    const float4* enc4 = (const float4*)enc;
    float4* es4 = (float4*)es;
#pragma unroll
    for (int i = 0; i < 8; i++) {
        int f4 = i * 128 + tid;
        int r = f4 >> 8, k4 = f4 & 255;
        es4[f4] = enc4[(bb0 + r) * 256 + k4];
    }
    __syncthreads();

    const int w = tid >> 5, lane = tid & 31;
    const float4* W14 = (const float4*)W1;

    for (int jj = 0; jj < 8; jj++) {
        int j = blockIdx.x * 32 + w * 8 + jj;
        float acc[4] = {0.f, 0.f, 0.f, 0.f};
#pragma unroll
        for (int i = 0; i < 8; i++) {
            float4 wv = W14[j * 256 + i * 32 + lane];
#pragma unroll
            for (int bbi = 0; bbi < 4; bbi++) {
                float4 ev = es4[bbi * 256 + i * 32 + lane];
                acc[bbi] += wv.x * ev.x + wv.y * ev.y + wv.z * ev.z + wv.w * ev.w;
            }
        }
#pragma unroll
        for (int bbi = 0; bbi < 4; bbi++) {
            float v = acc[bbi];
#pragma unroll
            for (int off = 16; off > 0; off >>= 1)
                v += __shfl_xor_sync(0xFFFFFFFFu, v, off);
            if (lane == 0) {
                float x = v + b1[j];
                float g = 0.5f * x * (1.0f + erff(x * 0.70710678118654752f));
                g_h[(bb0 + bbi) * HID + j] = g;
            }
        }
    }
}

// ---------------------------------------------------------------------------
// K2: q[b][d] = h[b] . W2[d]; store as bf16 hi/lo splits, row-major [b][d]
// ---------------------------------------------------------------------------
__global__ void k2_query(const float* __restrict__ W2) {
    __shared__ float hs[4 * HID];
    const int tid = threadIdx.x;
    const int bb0 = blockIdx.y * 4;

    const float4* h4 = (const float4*)g_h;
    float4* hs4 = (float4*)hs;
#pragma unroll
    for (int i = 0; i < 4; i++) {
        int f4 = i * 128 + tid;
        int r = f4 >> 7, k4 = f4 & 127;
        hs4[f4] = h4[(bb0 + r) * 128 + k4];
    }
    __syncthreads();

    const int w = tid >> 5, lane = tid & 31;
    const float4* W24 = (const float4*)W2;

    for (int dd = 0; dd < 8; dd++) {
        int d = blockIdx.x * 32 + w * 8 + dd;
        float acc[4] = {0.f, 0.f, 0.f, 0.f};
#pragma unroll
        for (int i = 0; i < 4; i++) {
            float4 wv = W24[d * 128 + i * 32 + lane];
#pragma unroll
            for (int bbi = 0; bbi < 4; bbi++) {
                float4 hv = hs4[bbi * 128 + i * 32 + lane];
                acc[bbi] += wv.x * hv.x + wv.y * hv.y + wv.z * hv.z + wv.w * hv.w;
            }
        }
#pragma unroll
        for (int bbi = 0; bbi < 4; bbi++) {
            float v = acc[bbi];
#pragma unroll
            for (int off = 16; off > 0; off >>= 1)
                v += __shfl_xor_sync(0xFFFFFFFFu, v, off);
            if (lane == 0) {
                int b = bb0 + bbi;
                __nv_bfloat16 h = __float2bfloat16(v);
                g_qh[b * TOK + d] = h;
                g_ql[b * TOK + d] = __float2bfloat16(v - __bfloat162float(h));
            }
        }
    }
}

// ---------------------------------------------------------------------------
// K3: P[t][b] = tok_emb[t] . q[b] via mma.sync bf16 3-pass split.
//   256 thr / 8 warps, M=256/block (32 rows per warp), N=32, K=256.
//   A fragments loaded DIRECTLY from gmem as float2 (each LDG.64 = 1 full
//   32B sector, each sector read exactly once), converted to bf16 hi/lo in
//   registers. Only q lives in smem. No barriers in the mainloop.
// ---------------------------------------------------------------------------
#define QROW_W 132          // 32-bit words per q row (264 bf16, conflict-free)

__global__ void __launch_bounds__(256, 2) k3_mma(const float* __restrict__ tok) {
    __shared__ uint32_t qsm[2 * 32 * QROW_W];      // hi | lo, 33792 B
    uint32_t* qh = qsm;
    uint32_t* ql = qsm + 32 * QROW_W;

    const int tid  = threadIdx.x;
    const int warp = tid >> 5, lane = tid & 31;
    const int gr   = lane >> 2;          // fragment row group 0..7
    const int kq   = lane & 3;           // fragment k quarter 0..3

    // Stage q hi/lo (2048 uint2 each, 8 iters of 256 thr)
    {
        const uint2* gq = (const uint2*)g_qh;
        const uint2* gl = (const uint2*)g_ql;
#pragma unroll
        for (int i = 0; i < 8; i++) {
            int idx2 = i * 256 + tid;            // 0..2047
            int n = idx2 >> 6;
            int k2 = (idx2 & 63) * 2;
            *(uint2*)&qh[n * QROW_W + k2] = gq[idx2];
            *(uint2*)&ql[n * QROW_W + k2] = gl[idx2];
        }
    }
    __syncthreads();

    float acc[2][4][4];
#pragma unroll
    for (int mt = 0; mt < 2; mt++)
#pragma unroll
        for (int nt = 0; nt < 4; nt++)
#pragma unroll
            for (int r = 0; r < 4; r++) acc[mt][nt][r] = 0.f;

    const int r0 = blockIdx.x * 256 + warp * 32;
    // Clamped source rows (stores are guarded separately)
    int ra[2], rb[2];
#pragma unroll
    for (int mt = 0; mt < 2; mt++) {
        int t = r0 + mt * 16 + gr;
        ra[mt] = (t < VOCAB) ? t : (VOCAB - 1);
        int u = t + 8;
        rb[mt] = (u < VOCAB) ? u : (VOCAB - 1);
    }

#pragma unroll 4
    for (int k16 = 0; k16 < 16; k16++) {
        const int col = k16 * 16 + kq * 2;

        // A fragments: direct gmem float2 loads + in-register bf16 split
        uint32_t fah[2][4], fal[2][4];
#pragma unroll
        for (int mt = 0; mt < 2; mt++) {
            const float2* pa = (const float2*)(tok + (size_t)ra[mt] * 256 + col);
            const float2* pb = (const float2*)(tok + (size_t)rb[mt] * 256 + col);
            float2 v0 = __ldcs(pa);          // (row gr,    k kq*2)
            float2 v1 = __ldcs(pb);          // (row gr+8,  k kq*2)
            float2 v2 = __ldcs(pa + 4);      // (row gr,    k kq*2+8)
            float2 v3 = __ldcs(pb + 4);      // (row gr+8,  k kq*2+8)
            cvt_split(v0.x, v0.y, fah[mt][0], fal[mt][0]);
            cvt_split(v1.x, v1.y, fah[mt][1], fal[mt][1]);
            cvt_split(v2.x, v2.y, fah[mt][2], fal[mt][2]);
            cvt_split(v3.x, v3.y, fah[mt][3], fal[mt][3]);
        }

        // B fragments (q) from smem
        uint32_t bh[4][2], bl[4][2];
        const int qw = k16 * 8 + kq;
#pragma unroll
        for (int nt = 0; nt < 4; nt++) {
            int w0 = (nt * 8 + gr) * QROW_W + qw;
            bh[nt][0] = qh[w0]; bh[nt][1] = qh[w0 + 4];
            bl[nt][0] = ql[w0]; bl[nt][1] = ql[w0 + 4];
        }

#pragma unroll
        for (int mt = 0; mt < 2; mt++)
#pragma unroll
            for (int nt = 0; nt < 4; nt++) {
                mma16816(acc[mt][nt], fah[mt], bh[nt]);
                mma16816(acc[mt][nt], fah[mt], bl[nt]);
                mma16816(acc[mt][nt], fal[mt], bh[nt]);
            }
    }

    // Epilogue: c0,c1 -> P[r0+mt*16+gr][nt*8+kq*2..+1]; c2,c3 -> row+8
#pragma unroll
    for (int mt = 0; mt < 2; mt++) {
        int ta = r0 + mt * 16 + gr;
        int tb = ta + 8;
#pragma unroll
        for (int nt = 0; nt < 4; nt++) {
            int colp = nt * 8 + kq * 2;
            if (ta < VOCAB)
                *(float2*)&g_P[(size_t)ta * 32 + colp] = make_float2(acc[mt][nt][0], acc[mt][nt][1]);
            if (tb < VOCAB)
                *(float2*)&g_P[(size_t)tb * 32 + colp] = make_float2(acc[mt][nt][2], acc[mt][nt][3]);
        }
    }
}

// ---------------------------------------------------------------------------
// K4: logits[b][c] = P[cand[b][c]][b], 8 elems/thread for MLP
// ---------------------------------------------------------------------------
__global__ void k4_gather(const int* __restrict__ cand,
                          float* __restrict__ out) {
    int base = blockIdx.x * 256 + threadIdx.x;   // 512 blocks x 256 thr
    int t[8];
#pragma unroll
    for (int j = 0; j < 8; j++) {
        int tt = __ldcs(&cand[base + j * 131072]);
        t[j] = (tt < 0) ? 0 : (tt >= VOCAB ? VOCAB - 1 : tt);
    }
    float v[8];
#pragma unroll
    for (int j = 0; j < 8; j++) {
        int g = base + j * 131072;
        int b = g >> 15;
        v[j] = g_P[(size_t)t[j] * 32 + b];
    }
#pragma unroll
    for (int j = 0; j < 8; j++)
        out[base + j * 131072] = v[j];
}

// ---------------------------------------------------------------------------
extern "C" void kernel_launch(void* const* d_in, const int* in_sizes, int n_in,
                              void* d_out, int out_size) {
    const float* enc  = (const float*)d_in[0];
    const int*   cand = (const int*)d_in[1];
    const float* tok  = (const float*)d_in[2];
    const float* W1   = (const float*)d_in[3];
    const float* b1   = (const float*)d_in[4];
    const float* W2   = (const float*)d_in[5];
    float* out = (float*)d_out;

    k1_hidden<<<dim3(16, 8), 128>>>(enc, W1, b1);
    k2_query<<<dim3(8, 8), 128>>>(W2);
    k3_mma<<<(VOCAB + 255) / 256, 256>>>(tok);
    k4_gather<<<512, 256>>>(cand, out);
}